// round 1
// baseline (speedup 1.0000x reference)
#include <cuda_runtime.h>
#include <math.h>

#define NN 50000
#define NE 800000
#define NE2 (NE + NN)
#define HCC 128
#define NEG_SLOPE 0.2f
#define BN_EPS 1e-5f

// ---------------- scratch (static device globals; no runtime allocation) ----------------
__device__ float g_xl[(size_t)NN * HCC];
__device__ float g_xr[(size_t)NN * HCC];
__device__ float g_h1[(size_t)NN * HCC];
__device__ float g_h2[(size_t)NN * HCC];
__device__ int   g_deg[NN];
__device__ int   g_off[NN + 1];
__device__ int   g_cur[NN];
__device__ int   g_eid[NE2];
__device__ float g_ps[128 * 128];
__device__ float g_pq[128 * 128];
__device__ float g_bna[HCC];
__device__ float g_bnb[HCC];
__device__ int   g_is64;

// ---------------- edge-index dtype detection (int64 vs int32) ----------------
__global__ void k_detect(const int* ei32) {
    if (threadIdx.x == 0 && blockIdx.x == 0) {
        int all0 = 1;
        for (int i = 1; i < 512; i += 2)
            if (ei32[i] != 0) { all0 = 0; break; }
        g_is64 = all0;
    }
}

__device__ __forceinline__ int edge_node(const void* ei, int i) {
    if (g_is64) return (int)((const long long*)ei)[i];
    return ((const int*)ei)[i];
}

// ---------------- CSR build ----------------
__global__ void k_zero_deg() {
    int i = blockIdx.x * blockDim.x + threadIdx.x;
    if (i < NN) g_deg[i] = 0;
}

__global__ void k_count(const void* ei) {
    int e = blockIdx.x * blockDim.x + threadIdx.x;
    if (e < NE) {
        int dst = edge_node(ei, NE + e);
        atomicAdd(&g_deg[dst], 1);
    }
}

__global__ void k_scan() {
    __shared__ int sh[1024];
    __shared__ int sbase;
    int t = threadIdx.x;
    if (t == 0) sbase = 0;
    __syncthreads();
    for (int start = 0; start < NN; start += 1024) {
        int i = start + t;
        int v = (i < NN) ? (g_deg[i] + 1) : 0;   // +1 for the self loop
        sh[t] = v;
        __syncthreads();
        for (int o = 1; o < 1024; o <<= 1) {
            int tmp = (t >= o) ? sh[t - o] : 0;
            __syncthreads();
            sh[t] += tmp;
            __syncthreads();
        }
        if (i < NN) g_off[i + 1] = sbase + sh[t];
        if (start == 0 && t == 0) g_off[0] = 0;
        __syncthreads();
        if (t == 1023) sbase += sh[1023];
        __syncthreads();
    }
}

__global__ void k_fill() {
    int v = blockIdx.x * blockDim.x + threadIdx.x;
    if (v < NN) {
        g_cur[v] = g_off[v];
        g_eid[g_off[v + 1] - 1] = NE + v;   // self loop in last slot
    }
}

__global__ void k_scatter(const void* ei) {
    int e = blockIdx.x * blockDim.x + threadIdx.x;
    if (e < NE) {
        int dst = edge_node(ei, NE + e);
        int pos = atomicAdd(&g_cur[dst], 1);
        g_eid[pos] = e;
    }
}

// ---------------- SGEMM: Y[M,128] = X[M,128] @ W[128,128] + b ----------------
__global__ void k_gemm(const float* __restrict__ X, const float* __restrict__ W,
                       const float* __restrict__ B, float* __restrict__ Y, int M) {
    __shared__ float As[8][129];
    __shared__ float Bs[8][128];
    int t  = threadIdx.x;           // 256 threads
    int m0 = blockIdx.x * 128;
    int tx = t & 15;                // n-tile
    int ty = t >> 4;                // m-tile

    float acc[8][8];
#pragma unroll
    for (int i = 0; i < 8; i++)
#pragma unroll
        for (int j = 0; j < 8; j++) acc[i][j] = 0.f;

    int ra = t >> 1, ka = (t & 1) * 4;   // A: float4 per thread
    int kb = t >> 5, nb = (t & 31) * 4;  // B: float4 per thread

    for (int k0 = 0; k0 < 128; k0 += 8) {
        float4 av = make_float4(0.f, 0.f, 0.f, 0.f);
        int row = m0 + ra;
        if (row < M) av = *(const float4*)(X + (size_t)row * 128 + k0 + ka);
        As[ka + 0][ra] = av.x; As[ka + 1][ra] = av.y;
        As[ka + 2][ra] = av.z; As[ka + 3][ra] = av.w;
        float4 bv = *(const float4*)(W + (size_t)(k0 + kb) * 128 + nb);
        *(float4*)(&Bs[kb][nb]) = bv;
        __syncthreads();
#pragma unroll
        for (int kk = 0; kk < 8; kk++) {
            float a[8], b[8];
#pragma unroll
            for (int i = 0; i < 8; i++) a[i] = As[kk][ty * 8 + i];
#pragma unroll
            for (int j = 0; j < 8; j++) b[j] = Bs[kk][tx * 8 + j];
#pragma unroll
            for (int i = 0; i < 8; i++)
#pragma unroll
                for (int j = 0; j < 8; j++) acc[i][j] += a[i] * b[j];
        }
        __syncthreads();
    }
#pragma unroll
    for (int i = 0; i < 8; i++) {
        int row = m0 + ty * 8 + i;
        if (row < M) {
#pragma unroll
            for (int j = 0; j < 8; j++)
                Y[(size_t)row * 128 + tx * 8 + j] = acc[i][j] + B[tx * 8 + j];
        }
    }
}

// ---------------- GATv2 attention: one node per warp, online softmax ----------------
__global__ void k_attn(const void* __restrict__ ei, const float* __restrict__ ew,
                       const float* __restrict__ xl, const float* __restrict__ xr,
                       const float* __restrict__ We, const float* __restrict__ att,
                       const float* __restrict__ bias, float* __restrict__ out) {
    int wid  = threadIdx.x >> 5;
    int lane = threadIdx.x & 31;
    int v = blockIdx.x * (blockDim.x >> 5) + wid;
    if (v >= NN) return;

    float xrv[4], attv[4], wev[4], bv[4];
#pragma unroll
    for (int j = 0; j < 4; j++) {
        int c = j * 32 + lane;
        xrv[j]  = xr[(size_t)v * HCC + c];
        attv[j] = att[c];
        wev[j]  = We[c];
        bv[j]   = bias[c];
    }

    int beg = g_off[v], end = g_off[v + 1];
    int degr = end - 1 - beg;     // real in-degree (excl. self loop)

    // self-loop weight = mean of incoming edge weights (0 if none)
    float ws = 0.f;
    for (int e = beg + lane; e < end - 1; e += 32) ws += ew[g_eid[e]];
#pragma unroll
    for (int o = 16; o; o >>= 1) ws += __shfl_xor_sync(0xffffffffu, ws, o);
    float loopw = ws / (float)max(degr, 1);

    float m[4], den[4], acc[4];
#pragma unroll
    for (int j = 0; j < 4; j++) { m[j] = -INFINITY; den[j] = 0.f; acc[j] = 0.f; }

    for (int e = beg; e < end; ++e) {
        int eid = g_eid[e];
        int src; float w;
        if (eid < NE) { src = edge_node(ei, eid); w = ew[eid]; }
        else          { src = v; w = loopw; }

        const float* xrow = xl + (size_t)src * HCC;
        float lg[4], xj[4];
#pragma unroll
        for (int j = 0; j < 4; j++) {
            xj[j] = xrow[j * 32 + lane];
            float msg = xj[j] + xrv[j] + w * wev[j];
            msg = msg > 0.f ? msg : NEG_SLOPE * msg;
            lg[j] = msg * attv[j];
        }
#pragma unroll
        for (int o = 16; o; o >>= 1) {
#pragma unroll
            for (int j = 0; j < 4; j++)
                lg[j] += __shfl_xor_sync(0xffffffffu, lg[j], o);
        }
#pragma unroll
        for (int j = 0; j < 4; j++) {
            float mn = fmaxf(m[j], lg[j]);
            float sc = __expf(m[j] - mn);
            float ex = __expf(lg[j] - mn);
            den[j] = den[j] * sc + ex;
            acc[j] = acc[j] * sc + ex * xj[j];
            m[j] = mn;
        }
    }
#pragma unroll
    for (int j = 0; j < 4; j++)
        out[(size_t)v * HCC + j * 32 + lane] = acc[j] / den[j] + bv[j];
}

// ---------------- BatchNorm stats (deterministic two-stage) ----------------
__global__ void k_bnstat() {
    __shared__ float ss[256], sq[256];
    const long long stride = 128LL * 256;   // grid fixed at 128 blocks x 256 threads
    float s = 0.f, q = 0.f;
    for (long long i = (long long)blockIdx.x * 256 + threadIdx.x;
         i < (long long)NN * HCC; i += stride) {
        float x = g_h1[i];
        s += x; q += x * x;
    }
    ss[threadIdx.x] = s; sq[threadIdx.x] = q;
    __syncthreads();
    if (threadIdx.x < 128) {
        g_ps[blockIdx.x * 128 + threadIdx.x] = ss[threadIdx.x] + ss[threadIdx.x + 128];
        g_pq[blockIdx.x * 128 + threadIdx.x] = sq[threadIdx.x] + sq[threadIdx.x + 128];
    }
}

__global__ void k_bnred(const float* __restrict__ gamma, const float* __restrict__ beta) {
    int c = threadIdx.x;
    if (c >= 128) return;
    float s = 0.f, q = 0.f;
    for (int b = 0; b < 128; b++) { s += g_ps[b * 128 + c]; q += g_pq[b * 128 + c]; }
    float mean = s / (float)NN;
    float var  = q / (float)NN - mean * mean;
    float a = gamma[c] * rsqrtf(var + BN_EPS);
    g_bna[c] = a;
    g_bnb[c] = beta[c] - mean * a;
}

__global__ void k_bnelu() {
    long long i = (long long)blockIdx.x * blockDim.x + threadIdx.x;
    if (i < (long long)NN * HCC) {
        int c = (int)(i & 127);
        float y = g_bna[c] * g_h1[i] + g_bnb[c];
        g_h1[i] = y > 0.f ? y : expm1f(y);
    }
}

// ---------------- final fuse: (emb + h1 + h2) / 3 ----------------
__global__ void k_final(const float* __restrict__ emb, float* __restrict__ out) {
    long long i = (long long)blockIdx.x * blockDim.x + threadIdx.x;
    if (i < (long long)NN * HCC)
        out[i] = (emb[i] + g_h1[i] + g_h2[i]) * (1.f / 3.f);
}

// ---------------- launch ----------------
extern "C" void kernel_launch(void* const* d_in, const int* in_sizes, int n_in,
                              void* d_out, int out_size) {
    const float* emb   = (const float*)d_in[0];
    const void*  ei    = d_in[1];
    const float* ew    = (const float*)d_in[2];
    const float* Wl1   = (const float*)d_in[3];
    const float* bl1   = (const float*)d_in[4];
    const float* Wr1   = (const float*)d_in[5];
    const float* br1   = (const float*)d_in[6];
    const float* We1   = (const float*)d_in[7];
    const float* att1  = (const float*)d_in[8];
    const float* bias1 = (const float*)d_in[9];
    const float* gam1  = (const float*)d_in[10];
    const float* bet1  = (const float*)d_in[11];
    const float* Wl2   = (const float*)d_in[12];
    const float* bl2   = (const float*)d_in[13];
    const float* Wr2   = (const float*)d_in[14];
    const float* br2   = (const float*)d_in[15];
    const float* We2   = (const float*)d_in[16];
    const float* att2  = (const float*)d_in[17];
    const float* bias2 = (const float*)d_in[18];
    float* out = (float*)d_out;

    float *p_xl, *p_xr, *p_h1, *p_h2;
    cudaGetSymbolAddress((void**)&p_xl, g_xl);
    cudaGetSymbolAddress((void**)&p_xr, g_xr);
    cudaGetSymbolAddress((void**)&p_h1, g_h1);
    cudaGetSymbolAddress((void**)&p_h2, g_h2);

    const int TB = 256;
    int gN  = (NN + TB - 1) / TB;
    int gE  = (NE + TB - 1) / TB;
    int gEl = (int)(((long long)NN * HCC + TB - 1) / TB);
    int gG  = (NN + 127) / 128;
    int gA  = (NN + 7) / 8;   // 8 warps per 256-thread block

    // dtype detect + CSR build
    k_detect<<<1, 32>>>((const int*)ei);
    k_zero_deg<<<gN, TB>>>();
    k_count<<<gE, TB>>>(ei);
    k_scan<<<1, 1024>>>();
    k_fill<<<gN, TB>>>();
    k_scatter<<<gE, TB>>>(ei);

    // layer 1
    k_gemm<<<gG, TB>>>(emb, Wl1, bl1, p_xl, NN);
    k_gemm<<<gG, TB>>>(emb, Wr1, br1, p_xr, NN);
    k_attn<<<gA, TB>>>(ei, ew, p_xl, p_xr, We1, att1, bias1, p_h1);

    // batchnorm + elu (in place on h1)
    k_bnstat<<<128, 256>>>();
    k_bnred<<<1, 128>>>(gam1, bet1);
    k_bnelu<<<gEl, TB>>>();

    // layer 2
    k_gemm<<<gG, TB>>>(p_h1, Wl2, bl2, p_xl, NN);
    k_gemm<<<gG, TB>>>(p_h1, Wr2, br2, p_xr, NN);
    k_attn<<<gA, TB>>>(ei, ew, p_xl, p_xr, We2, att2, bias2, p_h2);

    // fuse
    k_final<<<gEl, TB>>>(emb, out);
}

// round 3
// speedup vs baseline: 1.0495x; 1.0495x over previous
#include <cuda_runtime.h>
#include <math.h>

#define NN 50000
#define NE 800000
#define NE2 (NE + NN)
#define HCC 128
#define NEG_SLOPE 0.2f
#define BN_EPS 1e-5f
#define NBLK ((NN + 255) / 256)   // 196 scan blocks

// ---------------- scratch ----------------
__device__ float g_xl[(size_t)NN * HCC];
__device__ float g_xr[(size_t)NN * HCC];
__device__ float g_h1[(size_t)NN * HCC];
__device__ int   g_deg[NN];
__device__ int   g_off[NN + 1];
__device__ int   g_cur[NN];
__device__ int   g_eid[NE2];
__device__ int   g_bsum[NBLK];
__device__ float g_ps[128 * 128];
__device__ float g_pq[128 * 128];
__device__ float g_bna[HCC];
__device__ float g_bnb[HCC];
__device__ int   g_is64;

// ---------------- init: zero degrees + parallel dtype detect ----------------
__global__ void k_init(const int* ei32) {
    int i = blockIdx.x * blockDim.x + threadIdx.x;
    if (i < NN) g_deg[i] = 0;
    if (blockIdx.x == 0) {
        __shared__ int nz;
        if (threadIdx.x == 0) nz = 0;
        __syncthreads();
        // if int64, odd 32-bit words (high words of small positive values) are all 0
        if (ei32[2 * threadIdx.x + 1] != 0) atomicOr(&nz, 1);
        __syncthreads();
        if (threadIdx.x == 0) g_is64 = (nz == 0);
    }
}

__device__ __forceinline__ int edge_node(const void* ei, int i) {
    if (g_is64) return (int)((const long long*)ei)[i];
    return ((const int*)ei)[i];
}

// ---------------- CSR build ----------------
__global__ void k_count(const void* ei) {
    int e = blockIdx.x * blockDim.x + threadIdx.x;
    if (e < NE) atomicAdd(&g_deg[edge_node(ei, NE + e)], 1);
}

__device__ __forceinline__ int block_scan_inc(int v) {
    int t = threadIdx.x;
    int lane = t & 31, wid = t >> 5;
#pragma unroll
    for (int o = 1; o < 32; o <<= 1) {
        int n = __shfl_up_sync(0xffffffffu, v, o);
        if (lane >= o) v += n;
    }
    __shared__ int wsum[8];
    if (lane == 31) wsum[wid] = v;
    __syncthreads();
    if (t < 8) {
        int w = wsum[t];
#pragma unroll
        for (int o = 1; o < 8; o <<= 1) {
            int n = __shfl_up_sync(0xffu, w, o);
            if (t >= o) w += n;
        }
        wsum[t] = w;
    }
    __syncthreads();
    if (wid > 0) v += wsum[wid - 1];
    return v;
}

__global__ void k_scan1() {
    int i = blockIdx.x * 256 + threadIdx.x;
    int v = (i < NN) ? (g_deg[i] + 1) : 0;  // +1 self loop
    int s = block_scan_inc(v);
    if (i < NN) g_off[i + 1] = s;
    if (threadIdx.x == 255) g_bsum[blockIdx.x] = s;
}

__global__ void k_scan2() {
    int t = threadIdx.x;
    int v = (t < NBLK) ? g_bsum[t] : 0;
    int s = block_scan_inc(v);
    if (t < NBLK) g_bsum[t] = s;
}

__global__ void k_scan3() {
    int i = blockIdx.x * 256 + threadIdx.x;
    if (i == 0) g_off[0] = 0;
    if (i < NN && blockIdx.x > 0)
        g_off[i + 1] += g_bsum[blockIdx.x - 1];
}

__global__ void k_fill() {
    int v = blockIdx.x * blockDim.x + threadIdx.x;
    if (v < NN) {
        g_cur[v] = g_off[v];
        g_eid[g_off[v + 1] - 1] = NE + v;   // self loop in last slot
    }
}

__global__ void k_scatter(const void* ei) {
    int e = blockIdx.x * blockDim.x + threadIdx.x;
    if (e < NE) {
        int dst = edge_node(ei, NE + e);
        int pos = atomicAdd(&g_cur[dst], 1);
        g_eid[pos] = e;
    }
}

// ---------------- fused dual-weight SGEMM ----------------
// Y0 = f(X) @ W0 + B0 ; Y1 = f(X) @ W1 + B1,  f = identity or BN+ELU
// X tile [128,128] held in smem (m-major, stride 132); W streamed in K-chunks of 16.
__global__ void k_gemm2(const float* __restrict__ X,
                        const float* __restrict__ W0, const float* __restrict__ B0,
                        float* __restrict__ Y0,
                        const float* __restrict__ W1, const float* __restrict__ B1,
                        float* __restrict__ Y1, int M, int doBN) {
    extern __shared__ float sm[];
    float* As = sm;                  // [128][132]
    float* Bs = sm + 128 * 132;      // [16][128]

    int t  = threadIdx.x;            // 256
    int m0 = blockIdx.x * 128;
    int tx = t & 15, ty = t >> 4;

    // load X tile (with optional BN+ELU)
#pragma unroll
    for (int it = 0; it < 16; ++it) {
        int idx = it * 256 + t;
        int row = idx >> 5;
        int c4  = (idx & 31) * 4;
        float4 v = make_float4(0.f, 0.f, 0.f, 0.f);
        int gr = m0 + row;
        if (gr < M) v = *(const float4*)(X + (size_t)gr * 128 + c4);
        if (doBN) {
            float a0 = g_bna[c4], a1 = g_bna[c4 + 1], a2 = g_bna[c4 + 2], a3 = g_bna[c4 + 3];
            float b0 = g_bnb[c4], b1 = g_bnb[c4 + 1], b2 = g_bnb[c4 + 2], b3 = g_bnb[c4 + 3];
            v.x = a0 * v.x + b0; v.x = v.x > 0.f ? v.x : expm1f(v.x);
            v.y = a1 * v.y + b1; v.y = v.y > 0.f ? v.y : expm1f(v.y);
            v.z = a2 * v.z + b2; v.z = v.z > 0.f ? v.z : expm1f(v.z);
            v.w = a3 * v.w + b3; v.w = v.w > 0.f ? v.w : expm1f(v.w);
        }
        *(float4*)(As + row * 132 + c4) = v;
    }
    __syncthreads();

    for (int w = 0; w < 2; ++w) {
        const float* W = w ? W1 : W0;
        const float* B = w ? B1 : B0;
        float*       Y = w ? Y1 : Y0;

        float acc[8][8];
#pragma unroll
        for (int i = 0; i < 8; i++)
#pragma unroll
            for (int j = 0; j < 8; j++) acc[i][j] = 0.f;

        for (int kc = 0; kc < 8; ++kc) {
            __syncthreads();
            // load W chunk [16][128]: 512 float4 / 256 threads = 2 each
#pragma unroll
            for (int it = 0; it < 2; ++it) {
                int idx = it * 256 + t;          // 0..511
                int kk = idx >> 5;
                int n4 = (idx & 31) * 4;
                *(float4*)(Bs + kk * 128 + n4) =
                    *(const float4*)(W + (size_t)(kc * 16 + kk) * 128 + n4);
            }
            __syncthreads();
#pragma unroll
            for (int kk = 0; kk < 16; ++kk) {
                float a[8], b[8];
#pragma unroll
                for (int i = 0; i < 8; i++)
                    a[i] = As[(ty * 8 + i) * 132 + kc * 16 + kk];
                float4 b0 = *(float4*)(Bs + kk * 128 + tx * 8);
                float4 b1 = *(float4*)(Bs + kk * 128 + tx * 8 + 4);
                b[0] = b0.x; b[1] = b0.y; b[2] = b0.z; b[3] = b0.w;
                b[4] = b1.x; b[5] = b1.y; b[6] = b1.z; b[7] = b1.w;
#pragma unroll
                for (int i = 0; i < 8; i++)
#pragma unroll
                    for (int j = 0; j < 8; j++) acc[i][j] += a[i] * b[j];
            }
        }
#pragma unroll
        for (int i = 0; i < 8; i++) {
            int row = m0 + ty * 8 + i;
            if (row < M) {
#pragma unroll
                for (int j = 0; j < 8; j++)
                    Y[(size_t)row * 128 + tx * 8 + j] = acc[i][j] + B[tx * 8 + j];
            }
        }
    }
}

// ---------------- GATv2 attention: warp/node, lane owns 4 contiguous channels ----------------
// lane L -> channels 4L..4L+3, all within head L/8. Per-head logit = 8-lane segment reduce.
__global__ void k_attn(const void* __restrict__ ei, const float* __restrict__ ew,
                       const float* __restrict__ xl, const float* __restrict__ xr,
                       const float* __restrict__ We, const float* __restrict__ att,
                       const float* __restrict__ bias, float* __restrict__ out,
                       const float* __restrict__ emb, const float* __restrict__ h1raw,
                       int fuse) {
    int wid  = threadIdx.x >> 5;
    int lane = threadIdx.x & 31;
    int v = blockIdx.x * (blockDim.x >> 5) + wid;
    if (v >= NN) return;

    int c4 = lane * 4;
    float4 xrv  = *(const float4*)(xr + (size_t)v * HCC + c4);
    float4 attv = *(const float4*)(att + c4);
    float4 wev  = *(const float4*)(We + c4);
    float4 bv   = *(const float4*)(bias + c4);

    int beg = g_off[v], end = g_off[v + 1];
    int degr = end - 1 - beg;

    // self-loop weight = mean of real incoming edge weights
    float ws = 0.f;
    for (int e = beg + lane; e < end - 1; e += 32) ws += ew[g_eid[e]];
#pragma unroll
    for (int o = 16; o; o >>= 1) ws += __shfl_xor_sync(0xffffffffu, ws, o);
    float loopw = ws / (float)max(degr, 1);

    float m = -INFINITY, den = 0.f;
    float4 acc = make_float4(0.f, 0.f, 0.f, 0.f);

    // prefetch first edge
    int e = beg;
    int eid = g_eid[e];
    int src; float w;
    if (eid < NE) { src = edge_node(ei, eid); w = ew[eid]; }
    else          { src = v; w = loopw; }

    while (true) {
        float4 xj = *(const float4*)(xl + (size_t)src * HCC + c4);
        // prefetch next edge meta
        int e2 = e + 1;
        int src2 = 0; float w2 = 0.f;
        if (e2 < end) {
            int eid2 = g_eid[e2];
            if (eid2 < NE) { src2 = edge_node(ei, eid2); w2 = ew[eid2]; }
            else           { src2 = v; w2 = loopw; }
        }
        float mx = xj.x + xrv.x + w * wev.x; mx = mx > 0.f ? mx : NEG_SLOPE * mx;
        float my = xj.y + xrv.y + w * wev.y; my = my > 0.f ? my : NEG_SLOPE * my;
        float mz = xj.z + xrv.z + w * wev.z; mz = mz > 0.f ? mz : NEG_SLOPE * mz;
        float mw = xj.w + xrv.w + w * wev.w; mw = mw > 0.f ? mw : NEG_SLOPE * mw;
        float part = mx * attv.x + my * attv.y + mz * attv.z + mw * attv.w;
        part += __shfl_xor_sync(0xffffffffu, part, 1);
        part += __shfl_xor_sync(0xffffffffu, part, 2);
        part += __shfl_xor_sync(0xffffffffu, part, 4);
        // online softmax (per-head state, replicated across 8 lanes of segment)
        float mn = fmaxf(m, part);
        float sc = __expf(m - mn);
        float ex = __expf(part - mn);
        den = den * sc + ex;
        acc.x = acc.x * sc + ex * xj.x;
        acc.y = acc.y * sc + ex * xj.y;
        acc.z = acc.z * sc + ex * xj.z;
        acc.w = acc.w * sc + ex * xj.w;
        m = mn;
        if (e2 >= end) break;
        e = e2; src = src2; w = w2;
    }

    float inv = 1.f / den;
    float4 o4;
    o4.x = acc.x * inv + bv.x;
    o4.y = acc.y * inv + bv.y;
    o4.z = acc.z * inv + bv.z;
    o4.w = acc.w * inv + bv.w;

    if (fuse) {
        float4 e4 = *(const float4*)(emb + (size_t)v * HCC + c4);
        float4 h4 = *(const float4*)(h1raw + (size_t)v * HCC + c4);
        float4 a4 = *(const float4*)(g_bna + c4);
        float4 b4 = *(const float4*)(g_bnb + c4);
        float p;
        p = a4.x * h4.x + b4.x; p = p > 0.f ? p : expm1f(p); o4.x = (e4.x + p + o4.x) * (1.f / 3.f);
        p = a4.y * h4.y + b4.y; p = p > 0.f ? p : expm1f(p); o4.y = (e4.y + p + o4.y) * (1.f / 3.f);
        p = a4.z * h4.z + b4.z; p = p > 0.f ? p : expm1f(p); o4.z = (e4.z + p + o4.z) * (1.f / 3.f);
        p = a4.w * h4.w + b4.w; p = p > 0.f ? p : expm1f(p); o4.w = (e4.w + p + o4.w) * (1.f / 3.f);
    }
    *(float4*)(out + (size_t)v * HCC + c4) = o4;
}

// ---------------- BatchNorm stats (deterministic two-stage) ----------------
__global__ void k_bnstat() {
    __shared__ float ss[256], sq[256];
    const long long stride = 128LL * 256;
    float s = 0.f, q = 0.f;
    for (long long i = (long long)blockIdx.x * 256 + threadIdx.x;
         i < (long long)NN * HCC; i += stride) {
        float x = g_h1[i];
        s += x; q += x * x;
    }
    ss[threadIdx.x] = s; sq[threadIdx.x] = q;
    __syncthreads();
    if (threadIdx.x < 128) {
        g_ps[blockIdx.x * 128 + threadIdx.x] = ss[threadIdx.x] + ss[threadIdx.x + 128];
        g_pq[blockIdx.x * 128 + threadIdx.x] = sq[threadIdx.x] + sq[threadIdx.x + 128];
    }
}

__global__ void k_bnred(const float* __restrict__ gamma, const float* __restrict__ beta) {
    int c = threadIdx.x;
    if (c >= 128) return;
    float s = 0.f, q = 0.f;
    for (int b = 0; b < 128; b++) { s += g_ps[b * 128 + c]; q += g_pq[b * 128 + c]; }
    float mean = s / (float)NN;
    float var  = q / (float)NN - mean * mean;
    float a = gamma[c] * rsqrtf(var + BN_EPS);
    g_bna[c] = a;
    g_bnb[c] = beta[c] - mean * a;
}

// ---------------- launch ----------------
extern "C" void kernel_launch(void* const* d_in, const int* in_sizes, int n_in,
                              void* d_out, int out_size) {
    const float* emb   = (const float*)d_in[0];
    const void*  ei    = d_in[1];
    const float* ew    = (const float*)d_in[2];
    const float* Wl1   = (const float*)d_in[3];
    const float* bl1   = (const float*)d_in[4];
    const float* Wr1   = (const float*)d_in[5];
    const float* br1   = (const float*)d_in[6];
    const float* We1   = (const float*)d_in[7];
    const float* att1  = (const float*)d_in[8];
    const float* bias1 = (const float*)d_in[9];
    const float* gam1  = (const float*)d_in[10];
    const float* bet1  = (const float*)d_in[11];
    const float* Wl2   = (const float*)d_in[12];
    const float* bl2   = (const float*)d_in[13];
    const float* Wr2   = (const float*)d_in[14];
    const float* br2   = (const float*)d_in[15];
    const float* We2   = (const float*)d_in[16];
    const float* att2  = (const float*)d_in[17];
    const float* bias2 = (const float*)d_in[18];
    float* out = (float*)d_out;

    float *p_xl, *p_xr, *p_h1;
    cudaGetSymbolAddress((void**)&p_xl, g_xl);
    cudaGetSymbolAddress((void**)&p_xr, g_xr);
    cudaGetSymbolAddress((void**)&p_h1, g_h1);

    const int TB = 256;
    int gN  = (NN + TB - 1) / TB;
    int gE  = (NE + TB - 1) / TB;
    int gG  = (NN + 127) / 128;
    int gA  = (NN + 7) / 8;

    const int GEMM_SMEM = (128 * 132 + 16 * 128) * 4;  // 75776 B
    static int smem_set = 0;
    if (!smem_set) {
        cudaFuncSetAttribute(k_gemm2, cudaFuncAttributeMaxDynamicSharedMemorySize, GEMM_SMEM);
        smem_set = 1;
    }

    // CSR build
    k_init<<<gN, TB>>>((const int*)ei);
    k_count<<<gE, TB>>>(ei);
    k_scan1<<<NBLK, 256>>>();
    k_scan2<<<1, 256>>>();
    k_scan3<<<NBLK, 256>>>();
    k_fill<<<gN, TB>>>();
    k_scatter<<<gE, TB>>>(ei);

    // layer 1: xl/xr GEMMs + attention
    k_gemm2<<<gG, TB, GEMM_SMEM>>>(emb, Wl1, bl1, p_xl, Wr1, br1, p_xr, NN, 0);
    k_attn<<<gA, TB>>>(ei, ew, p_xl, p_xr, We1, att1, bias1, p_h1, nullptr, nullptr, 0);

    // BN stats
    k_bnstat<<<128, 256>>>();
    k_bnred<<<1, 128>>>(gam1, bet1);

    // layer 2: BN+ELU fused into GEMM A-load; final fuse in attn epilogue
    k_gemm2<<<gG, TB, GEMM_SMEM>>>(p_h1, Wl2, bl2, p_xl, Wr2, br2, p_xr, NN, 1);
    k_attn<<<gA, TB>>>(ei, ew, p_xl, p_xr, We2, att2, bias2, out, emb, p_h1, 1);
}

// round 4
// speedup vs baseline: 2.4879x; 2.3705x over previous
#include <cuda_runtime.h>
#include <math.h>

#define NN 50000
#define NE 800000
#define NE2 (NE + NN)
#define HCC 128
#define NEG_SLOPE 0.2f
#define BN_EPS 1e-5f
#define NBLK ((NN + 255) / 256)   // 196 scan blocks

// ---------------- scratch ----------------
__device__ float g_xl[(size_t)NN * HCC];
__device__ float g_xr[(size_t)NN * HCC];
__device__ float g_h1[(size_t)NN * HCC];
__device__ int   g_deg[NN];
__device__ int   g_off[NN + 1];
__device__ int   g_cur[NN];
__device__ int   g_eid[NE2];
__device__ int   g_bsum[NBLK];
__device__ float g_ps[128 * 128];
__device__ float g_pq[128 * 128];
__device__ float g_bna[HCC];
__device__ float g_bnb[HCC];
__device__ int   g_is64;

// ---------------- init: zero degrees + parallel dtype detect ----------------
__global__ void k_init(const int* ei32) {
    int i = blockIdx.x * blockDim.x + threadIdx.x;
    if (i < NN) g_deg[i] = 0;
    if (blockIdx.x == 0) {
        __shared__ int nz;
        if (threadIdx.x == 0) nz = 0;
        __syncthreads();
        if (ei32[2 * threadIdx.x + 1] != 0) atomicOr(&nz, 1);
        __syncthreads();
        if (threadIdx.x == 0) g_is64 = (nz == 0);
    }
}

__device__ __forceinline__ int edge_node(const void* ei, int i) {
    if (g_is64) return (int)((const long long*)ei)[i];
    return ((const int*)ei)[i];
}

// ---------------- CSR build ----------------
__global__ void k_count(const void* ei) {
    int e = blockIdx.x * blockDim.x + threadIdx.x;
    if (e < NE) atomicAdd(&g_deg[edge_node(ei, NE + e)], 1);
}

__device__ __forceinline__ int block_scan_inc(int v) {
    int t = threadIdx.x;
    int lane = t & 31, wid = t >> 5;
#pragma unroll
    for (int o = 1; o < 32; o <<= 1) {
        int n = __shfl_up_sync(0xffffffffu, v, o);
        if (lane >= o) v += n;
    }
    __shared__ int wsum[8];
    if (lane == 31) wsum[wid] = v;
    __syncthreads();
    if (t < 8) {
        int w = wsum[t];
#pragma unroll
        for (int o = 1; o < 8; o <<= 1) {
            int n = __shfl_up_sync(0xffu, w, o);
            if (t >= o) w += n;
        }
        wsum[t] = w;
    }
    __syncthreads();
    if (wid > 0) v += wsum[wid - 1];
    return v;
}

__global__ void k_scan1() {
    int i = blockIdx.x * 256 + threadIdx.x;
    int v = (i < NN) ? (g_deg[i] + 1) : 0;  // +1 self loop
    int s = block_scan_inc(v);
    if (i < NN) g_off[i + 1] = s;
    if (threadIdx.x == 255) g_bsum[blockIdx.x] = s;
}

__global__ void k_scan2() {
    int t = threadIdx.x;
    int v = (t < NBLK) ? g_bsum[t] : 0;
    int s = block_scan_inc(v);
    if (t < NBLK) g_bsum[t] = s;
}

// scan3 + fill fused: finalize offsets, init cursors, place self-loop ids
__global__ void k_scan3() {
    int i = blockIdx.x * 256 + threadIdx.x;
    if (i == 0) g_off[0] = 0;
    if (i < NN) {
        int o = g_off[i + 1];
        if (blockIdx.x > 0) o += g_bsum[blockIdx.x - 1];
        g_off[i + 1] = o;
        int b = o - (g_deg[i] + 1);
        g_cur[i] = b;
        g_eid[o - 1] = NE + i;   // self loop in last slot
    }
}

__global__ void k_scatter(const void* ei) {
    int e = blockIdx.x * blockDim.x + threadIdx.x;
    if (e < NE) {
        int dst = edge_node(ei, NE + e);
        int pos = atomicAdd(&g_cur[dst], 1);
        g_eid[pos] = e;
    }
}

// ---------------- tf32 tensor-core dual-weight GEMM ----------------
__device__ __forceinline__ float tf32r(float x) {
    float r;
    asm("cvt.rna.tf32.f32 %0, %1;" : "=f"(r) : "f"(x));
    return r;
}

__device__ __forceinline__ void mma_tf32(float* d, const float* a, float b0f, float b1f) {
    unsigned a0 = __float_as_uint(a[0]), a1 = __float_as_uint(a[1]);
    unsigned a2 = __float_as_uint(a[2]), a3 = __float_as_uint(a[3]);
    unsigned b0 = __float_as_uint(b0f),  b1 = __float_as_uint(b1f);
    asm("mma.sync.aligned.m16n8k8.row.col.f32.tf32.tf32.f32 "
        "{%0,%1,%2,%3}, {%4,%5,%6,%7}, {%8,%9}, {%0,%1,%2,%3};"
        : "+f"(d[0]), "+f"(d[1]), "+f"(d[2]), "+f"(d[3])
        : "r"(a0), "r"(a1), "r"(a2), "r"(a3), "r"(b0), "r"(b1));
}

#define AS_STR 132
#define BS_STR 136
#define GEMM_SMEM ((128 * AS_STR + 128 * BS_STR) * 4)

// Y0 = f(X) @ W0 + B0 ; Y1 = f(X) @ W1 + B1,  f = identity or BN+ELU
__global__ void k_gemm2(const float* __restrict__ X,
                        const float* __restrict__ W0, const float* __restrict__ B0,
                        float* __restrict__ Y0,
                        const float* __restrict__ W1, const float* __restrict__ B1,
                        float* __restrict__ Y1, int M, int doBN) {
    extern __shared__ float sm[];
    float* As = sm;                    // [128 m][AS_STR], m-major
    float* Bs = sm + 128 * AS_STR;     // [128 k][BS_STR], k-major

    int t    = threadIdx.x;            // 256 threads, 8 warps
    int m0   = blockIdx.x * 128;
    int lane = t & 31, wid = t >> 5;
    int g    = lane >> 2, tig = lane & 3;
    int wm   = (wid & 3) * 32;         // warp m offset (4 warps along m)
    int wn   = (wid >> 2) * 64;        // warp n offset (2 warps along n)

    // load X tile -> As (tf32), optional BN+ELU
#pragma unroll
    for (int it = 0; it < 16; ++it) {
        int idx = it * 256 + t;
        int row = idx >> 5;
        int c4  = (idx & 31) * 4;
        float4 v = make_float4(0.f, 0.f, 0.f, 0.f);
        int gr = m0 + row;
        if (gr < M) v = *(const float4*)(X + (size_t)gr * 128 + c4);
        if (doBN) {
            float4 a4 = *(float4*)(g_bna + c4);
            float4 b4 = *(float4*)(g_bnb + c4);
            v.x = a4.x * v.x + b4.x; v.x = v.x > 0.f ? v.x : expm1f(v.x);
            v.y = a4.y * v.y + b4.y; v.y = v.y > 0.f ? v.y : expm1f(v.y);
            v.z = a4.z * v.z + b4.z; v.z = v.z > 0.f ? v.z : expm1f(v.z);
            v.w = a4.w * v.w + b4.w; v.w = v.w > 0.f ? v.w : expm1f(v.w);
        }
        v.x = tf32r(v.x); v.y = tf32r(v.y); v.z = tf32r(v.z); v.w = tf32r(v.w);
        *(float4*)(As + row * AS_STR + c4) = v;
    }

    for (int w = 0; w < 2; ++w) {
        const float* W = w ? W1 : W0;
        const float* B = w ? B1 : B0;
        float*       Y = w ? Y1 : Y0;

        __syncthreads();
        // load W [k][n] -> Bs (tf32)
#pragma unroll
        for (int it = 0; it < 16; ++it) {
            int idx = it * 256 + t;
            int k  = idx >> 5;
            int c4 = (idx & 31) * 4;
            float4 v = *(const float4*)(W + (size_t)k * 128 + c4);
            v.x = tf32r(v.x); v.y = tf32r(v.y); v.z = tf32r(v.z); v.w = tf32r(v.w);
            *(float4*)(Bs + k * BS_STR + c4) = v;
        }
        __syncthreads();

        float acc[2][8][4];
#pragma unroll
        for (int mt = 0; mt < 2; mt++)
#pragma unroll
            for (int nt = 0; nt < 8; nt++)
#pragma unroll
                for (int q = 0; q < 4; q++) acc[mt][nt][q] = 0.f;

#pragma unroll
        for (int ks = 0; ks < 16; ++ks) {
            int kk = ks * 8;
            float a[2][4];
#pragma unroll
            for (int mt = 0; mt < 2; mt++) {
                const float* ap = As + (wm + mt * 16 + g) * AS_STR + kk + tig;
                a[mt][0] = ap[0];
                a[mt][1] = ap[8 * AS_STR];
                a[mt][2] = ap[4];
                a[mt][3] = ap[8 * AS_STR + 4];
            }
#pragma unroll
            for (int nt = 0; nt < 8; nt++) {
                int n = wn + nt * 8 + g;
                float b0 = Bs[(kk + tig) * BS_STR + n];
                float b1 = Bs[(kk + tig + 4) * BS_STR + n];
                mma_tf32(acc[0][nt], a[0], b0, b1);
                mma_tf32(acc[1][nt], a[1], b0, b1);
            }
        }

        // epilogue: bias + store
#pragma unroll
        for (int mt = 0; mt < 2; mt++) {
            int r0 = m0 + wm + mt * 16 + g;
#pragma unroll
            for (int nt = 0; nt < 8; nt++) {
                int c = wn + nt * 8 + 2 * tig;
                float bb0 = B[c], bb1 = B[c + 1];
                if (r0 < M) {
                    Y[(size_t)r0 * 128 + c]     = acc[mt][nt][0] + bb0;
                    Y[(size_t)r0 * 128 + c + 1] = acc[mt][nt][1] + bb1;
                }
                if (r0 + 8 < M) {
                    Y[(size_t)(r0 + 8) * 128 + c]     = acc[mt][nt][2] + bb0;
                    Y[(size_t)(r0 + 8) * 128 + c + 1] = acc[mt][nt][3] + bb1;
                }
            }
        }
    }
}

// ---------------- GATv2 attention: warp/node, lane owns 4 contiguous channels ----------------
__global__ void k_attn(const void* __restrict__ ei, const float* __restrict__ ew,
                       const float* __restrict__ xl, const float* __restrict__ xr,
                       const float* __restrict__ We, const float* __restrict__ att,
                       const float* __restrict__ bias, float* __restrict__ out,
                       const float* __restrict__ emb, const float* __restrict__ h1raw,
                       int fuse) {
    int wid  = threadIdx.x >> 5;
    int lane = threadIdx.x & 31;
    int v = blockIdx.x * (blockDim.x >> 5) + wid;
    if (v >= NN) return;

    int c4 = lane * 4;
    float4 xrv  = *(const float4*)(xr + (size_t)v * HCC + c4);
    float4 attv = *(const float4*)(att + c4);
    float4 wev  = *(const float4*)(We + c4);
    float4 bv   = *(const float4*)(bias + c4);

    int beg = g_off[v], end = g_off[v + 1];
    int degr = end - 1 - beg;

    float ws = 0.f;
    for (int e = beg + lane; e < end - 1; e += 32) ws += ew[g_eid[e]];
#pragma unroll
    for (int o = 16; o; o >>= 1) ws += __shfl_xor_sync(0xffffffffu, ws, o);
    float loopw = ws / (float)max(degr, 1);

    float m = -INFINITY, den = 0.f;
    float4 acc = make_float4(0.f, 0.f, 0.f, 0.f);

    int e = beg;
    int eid = g_eid[e];
    int src; float w;
    if (eid < NE) { src = edge_node(ei, eid); w = ew[eid]; }
    else          { src = v; w = loopw; }

    while (true) {
        float4 xj = *(const float4*)(xl + (size_t)src * HCC + c4);
        int e2 = e + 1;
        int src2 = 0; float w2 = 0.f;
        if (e2 < end) {
            int eid2 = g_eid[e2];
            if (eid2 < NE) { src2 = edge_node(ei, eid2); w2 = ew[eid2]; }
            else           { src2 = v; w2 = loopw; }
        }
        float mx = xj.x + xrv.x + w * wev.x; mx = mx > 0.f ? mx : NEG_SLOPE * mx;
        float my = xj.y + xrv.y + w * wev.y; my = my > 0.f ? my : NEG_SLOPE * my;
        float mz = xj.z + xrv.z + w * wev.z; mz = mz > 0.f ? mz : NEG_SLOPE * mz;
        float mw = xj.w + xrv.w + w * wev.w; mw = mw > 0.f ? mw : NEG_SLOPE * mw;
        float part = mx * attv.x + my * attv.y + mz * attv.z + mw * attv.w;
        part += __shfl_xor_sync(0xffffffffu, part, 1);
        part += __shfl_xor_sync(0xffffffffu, part, 2);
        part += __shfl_xor_sync(0xffffffffu, part, 4);
        float mn = fmaxf(m, part);
        float sc = __expf(m - mn);
        float ex = __expf(part - mn);
        den = den * sc + ex;
        acc.x = acc.x * sc + ex * xj.x;
        acc.y = acc.y * sc + ex * xj.y;
        acc.z = acc.z * sc + ex * xj.z;
        acc.w = acc.w * sc + ex * xj.w;
        m = mn;
        if (e2 >= end) break;
        e = e2; src = src2; w = w2;
    }

    float inv = 1.f / den;
    float4 o4;
    o4.x = acc.x * inv + bv.x;
    o4.y = acc.y * inv + bv.y;
    o4.z = acc.z * inv + bv.z;
    o4.w = acc.w * inv + bv.w;

    if (fuse) {
        float4 e4 = *(const float4*)(emb + (size_t)v * HCC + c4);
        float4 h4 = *(const float4*)(h1raw + (size_t)v * HCC + c4);
        float4 a4 = *(const float4*)(g_bna + c4);
        float4 b4 = *(const float4*)(g_bnb + c4);
        float p;
        p = a4.x * h4.x + b4.x; p = p > 0.f ? p : expm1f(p); o4.x = (e4.x + p + o4.x) * (1.f / 3.f);
        p = a4.y * h4.y + b4.y; p = p > 0.f ? p : expm1f(p); o4.y = (e4.y + p + o4.y) * (1.f / 3.f);
        p = a4.z * h4.z + b4.z; p = p > 0.f ? p : expm1f(p); o4.z = (e4.z + p + o4.z) * (1.f / 3.f);
        p = a4.w * h4.w + b4.w; p = p > 0.f ? p : expm1f(p); o4.w = (e4.w + p + o4.w) * (1.f / 3.f);
    }
    *(float4*)(out + (size_t)v * HCC + c4) = o4;
}

// ---------------- BatchNorm stats (deterministic two-stage) ----------------
__global__ void k_bnstat() {
    __shared__ float ss[256], sq[256];
    const long long stride = 128LL * 256;
    float s = 0.f, q = 0.f;
    for (long long i = (long long)blockIdx.x * 256 + threadIdx.x;
         i < (long long)NN * HCC; i += stride) {
        float x = g_h1[i];
        s += x; q += x * x;
    }
    ss[threadIdx.x] = s; sq[threadIdx.x] = q;
    __syncthreads();
    if (threadIdx.x < 128) {
        g_ps[blockIdx.x * 128 + threadIdx.x] = ss[threadIdx.x] + ss[threadIdx.x + 128];
        g_pq[blockIdx.x * 128 + threadIdx.x] = sq[threadIdx.x] + sq[threadIdx.x + 128];
    }
}

__global__ void k_bnred(const float* __restrict__ gamma, const float* __restrict__ beta) {
    int c = threadIdx.x;
    if (c >= 128) return;
    float s = 0.f, q = 0.f;
    for (int b = 0; b < 128; b++) { s += g_ps[b * 128 + c]; q += g_pq[b * 128 + c]; }
    float mean = s / (float)NN;
    float var  = q / (float)NN - mean * mean;
    float a = gamma[c] * rsqrtf(var + BN_EPS);
    g_bna[c] = a;
    g_bnb[c] = beta[c] - mean * a;
}

// ---------------- launch ----------------
extern "C" void kernel_launch(void* const* d_in, const int* in_sizes, int n_in,
                              void* d_out, int out_size) {
    const float* emb   = (const float*)d_in[0];
    const void*  ei    = d_in[1];
    const float* ew    = (const float*)d_in[2];
    const float* Wl1   = (const float*)d_in[3];
    const float* bl1   = (const float*)d_in[4];
    const float* Wr1   = (const float*)d_in[5];
    const float* br1   = (const float*)d_in[6];
    const float* We1   = (const float*)d_in[7];
    const float* att1  = (const float*)d_in[8];
    const float* bias1 = (const float*)d_in[9];
    const float* gam1  = (const float*)d_in[10];
    const float* bet1  = (const float*)d_in[11];
    const float* Wl2   = (const float*)d_in[12];
    const float* bl2   = (const float*)d_in[13];
    const float* Wr2   = (const float*)d_in[14];
    const float* br2   = (const float*)d_in[15];
    const float* We2   = (const float*)d_in[16];
    const float* att2  = (const float*)d_in[17];
    const float* bias2 = (const float*)d_in[18];
    float* out = (float*)d_out;

    float *p_xl, *p_xr, *p_h1;
    cudaGetSymbolAddress((void**)&p_xl, g_xl);
    cudaGetSymbolAddress((void**)&p_xr, g_xr);
    cudaGetSymbolAddress((void**)&p_h1, g_h1);

    const int TB = 256;
    int gN = (NN + TB - 1) / TB;
    int gE = (NE + TB - 1) / TB;
    int gG = (NN + 127) / 128;
    int gA = (NN + 7) / 8;

    static int smem_set = 0;
    if (!smem_set) {
        cudaFuncSetAttribute(k_gemm2, cudaFuncAttributeMaxDynamicSharedMemorySize, GEMM_SMEM);
        smem_set = 1;
    }

    // CSR build interleaved with layer-1 GEMM (gemm is launch #4 for ncu)
    k_init<<<gN, TB>>>((const int*)ei);
    k_count<<<gE, TB>>>(ei);
    k_scan1<<<NBLK, 256>>>();
    k_gemm2<<<gG, TB, GEMM_SMEM>>>(emb, Wl1, bl1, p_xl, Wr1, br1, p_xr, NN, 0);
    k_scan2<<<1, 256>>>();
    k_scan3<<<NBLK, 256>>>();
    k_scatter<<<gE, TB>>>(ei);

    // layer 1 attention
    k_attn<<<gA, TB>>>(ei, ew, p_xl, p_xr, We1, att1, bias1, p_h1, nullptr, nullptr, 0);

    // BN stats
    k_bnstat<<<128, 256>>>();
    k_bnred<<<1, 128>>>(gam1, bet1);

    // layer 2: BN+ELU fused into GEMM A-load; final fuse in attn epilogue
    k_gemm2<<<gG, TB, GEMM_SMEM>>>(p_h1, Wl2, bl2, p_xl, Wr2, br2, p_xr, NN, 1);
    k_attn<<<gA, TB>>>(ei, ew, p_xl, p_xr, We2, att2, bias2, out, emb, p_h1, 1);
}